// round 13
// baseline (speedup 1.0000x reference)
#include <cuda_runtime.h>
#include <cuda_bf16.h>
#include <cstdint>

#define B_   32
#define S_   512
#define E_   8
#define H_   768
#define KG_  100
#define MH_  1000
#define NROW 256
#define MHP  1024            /* padded hidden */
#define K1P  128             /* k1 K padded  */
#define KP1E 136             /* k1 smem pitch (elements), 272B: conflict-free */
#define KP2E 264             /* k2 smem pitch (elements), 528B: conflict-free */

// Scratch (device globals — no allocation allowed)
__device__ __align__(16) __nv_bfloat16 g_Xh[NROW * K1P];
__device__ __align__(16) __nv_bfloat16 g_Xl[NROW * K1P];
__device__ __align__(16) __nv_bfloat16 g_W1h[MHP * K1P];   // [n][k]
__device__ __align__(16) __nv_bfloat16 g_W1l[MHP * K1P];
__device__ __align__(16) __nv_bfloat16 g_W2h[H_ * MHP];    // [n][k]
__device__ __align__(16) __nv_bfloat16 g_W2l[H_ * MHP];
__device__ __align__(16) __nv_bfloat16 g_Hs_hi[NROW * MHP];
__device__ __align__(16) __nv_bfloat16 g_Hs_lo[NROW * MHP];
__device__ __align__(16) float g_ENT2[2][NROW * H_];

// ---------------- helpers ---------------------------------------------------
__device__ __forceinline__ uint32_t smem_u32(const void* p) {
    uint32_t a;
    asm("{ .reg .u64 t; cvta.to.shared.u64 t, %1; cvt.u32.u64 %0, t; }"
        : "=r"(a) : "l"(p));
    return a;
}
__device__ __forceinline__ void splitbf(float x, unsigned short& h,
                                        unsigned short& l) {
    __nv_bfloat16 hb = __float2bfloat16(x);
    float r = x - __bfloat162float(hb);
    __nv_bfloat16 lb = __float2bfloat16(r);
    h = *(unsigned short*)&hb;
    l = *(unsigned short*)&lb;
}
__device__ __forceinline__ void ldm_x4(uint32_t* r, uint32_t addr) {
    asm volatile("ldmatrix.sync.aligned.m8n8.x4.shared.b16 {%0,%1,%2,%3}, [%4];"
                 : "=r"(r[0]), "=r"(r[1]), "=r"(r[2]), "=r"(r[3]) : "r"(addr));
}
__device__ __forceinline__ void ldm_x2(uint32_t* r, uint32_t addr) {
    asm volatile("ldmatrix.sync.aligned.m8n8.x2.shared.b16 {%0,%1}, [%2];"
                 : "=r"(r[0]), "=r"(r[1]) : "r"(addr));
}
__device__ __forceinline__ void mma16816(float* c, const uint32_t* a,
                                         const uint32_t* b) {
    asm volatile(
        "mma.sync.aligned.m16n8k16.row.col.f32.bf16.bf16.f32 "
        "{%0,%1,%2,%3}, {%4,%5,%6,%7}, {%8,%9}, {%0,%1,%2,%3};"
        : "+f"(c[0]), "+f"(c[1]), "+f"(c[2]), "+f"(c[3])
        : "r"(a[0]), "r"(a[1]), "r"(a[2]), "r"(a[3]), "r"(b[0]), "r"(b[1]));
}

// ---------------------------------------------------------------------------
// kprep: split EVERYTHING once.  (unchanged, passing)
// ---------------------------------------------------------------------------
__global__ void __launch_bounds__(256) kprep(const float* __restrict__ W2,
                                             const float* __restrict__ W1,
                                             const float* __restrict__ X) {
    __shared__ unsigned short sh[32][33], sl[32][33];
    const int bid = blockIdx.x;
    const int tx = threadIdx.x, ty = threadIdx.y;

    if (bid < 768) {
        const int k0 = (bid & 31) * 32, n0 = (bid >> 5) * 32;
        #pragma unroll
        for (int j = 0; j < 4; j++) {
            int k = k0 + ty + j * 8;
            float v = (k < MH_) ? __ldg(W2 + (long long)k * H_ + n0 + tx) : 0.0f;
            unsigned short h, l; splitbf(v, h, l);
            sh[ty + j * 8][tx] = h; sl[ty + j * 8][tx] = l;
        }
        __syncthreads();
        #pragma unroll
        for (int j = 0; j < 4; j++) {
            int nn = ty + j * 8;
            g_W2h[(n0 + nn) * MHP + k0 + tx] = *(__nv_bfloat16*)&sh[tx][nn];
            g_W2l[(n0 + nn) * MHP + k0 + tx] = *(__nv_bfloat16*)&sl[tx][nn];
        }
    } else if (bid < 896) {
        const int t = bid - 768;
        const int k0 = (t & 3) * 32, n0 = (t >> 2) * 32;
        #pragma unroll
        for (int j = 0; j < 4; j++) {
            int k = k0 + ty + j * 8;
            float v = (k < KG_ && (n0 + tx) < MH_) ? __ldg(W1 + k * MH_ + n0 + tx)
                                                   : 0.0f;
            unsigned short h, l; splitbf(v, h, l);
            sh[ty + j * 8][tx] = h; sl[ty + j * 8][tx] = l;
        }
        __syncthreads();
        #pragma unroll
        for (int j = 0; j < 4; j++) {
            int nn = ty + j * 8;
            g_W1h[(n0 + nn) * K1P + k0 + tx] = *(__nv_bfloat16*)&sh[tx][nn];
            g_W1l[(n0 + nn) * K1P + k0 + tx] = *(__nv_bfloat16*)&sl[tx][nn];
        }
    } else {
        const int t = bid - 896;
        const int r0 = (t >> 2) * 32, k0 = (t & 3) * 32;
        #pragma unroll
        for (int j = 0; j < 4; j++) {
            int r = r0 + ty + j * 8, k = k0 + tx;
            float v = (k < KG_) ? __ldg(X + r * KG_ + k) : 0.0f;
            unsigned short h, l; splitbf(v, h, l);
            g_Xh[r * K1P + k] = *(__nv_bfloat16*)&h;
            g_Xl[r * K1P + k] = *(__nv_bfloat16*)&l;
        }
    }
}

// ---------------------------------------------------------------------------
// K1 (HMMA): unchanged, passing.
// ---------------------------------------------------------------------------
#define SM1_AL (32 * KP1E * 2)
#define SM1_BH (2 * SM1_AL)
#define SM1_BL (SM1_BH + 128 * KP1E * 2)
#define SMEM1  (SM1_BL + 128 * KP1E * 2)

__global__ void __launch_bounds__(128) k1_mma(const float* __restrict__ b1) {
    extern __shared__ char dsm[];
    const uint32_t sb = smem_u32(dsm);
    const int tid = threadIdx.x;
    const int lane = tid & 31, wid = tid >> 5;
    const int rb = blockIdx.x * 32;
    const int n0 = blockIdx.y * 128;

    #pragma unroll
    for (int i = 0; i < 4; i++) {
        int idx = tid + i * 128;
        int r = idx >> 4, c = idx & 15;
        uint4 vh = *(const uint4*)(g_Xh + (rb + r) * K1P + c * 8);
        uint4 vl = *(const uint4*)(g_Xl + (rb + r) * K1P + c * 8);
        *(uint4*)(dsm + (r * KP1E + c * 8) * 2)          = vh;
        *(uint4*)(dsm + SM1_AL + (r * KP1E + c * 8) * 2) = vl;
    }
    #pragma unroll
    for (int i = 0; i < 16; i++) {
        int idx = tid + i * 128;
        int n = idx >> 4, c = idx & 15;
        uint4 vh = *(const uint4*)(g_W1h + (n0 + n) * K1P + c * 8);
        uint4 vl = *(const uint4*)(g_W1l + (n0 + n) * K1P + c * 8);
        *(uint4*)(dsm + SM1_BH + (n * KP1E + c * 8) * 2) = vh;
        *(uint4*)(dsm + SM1_BL + (n * KP1E + c * 8) * 2) = vl;
    }
    __syncthreads();

    const int n_w = wid * 32;
    float acc[2][4][4];
    #pragma unroll
    for (int i = 0; i < 2; i++)
        #pragma unroll
        for (int j = 0; j < 4; j++)
            #pragma unroll
            for (int q = 0; q < 4; q++) acc[i][j][q] = 0.0f;

    const uint32_t arow = lane & 15;
    const uint32_t akof = (lane >> 4) << 3;
    const uint32_t brow = lane & 7;
    const uint32_t bkof = ((lane >> 3) & 1) << 3;

    #pragma unroll
    for (int ks = 0; ks < 8; ks++) {
        const uint32_t kk = ks * 16;
        uint32_t ah[2][4], al[2][4], bh[4][2], bl[4][2];
        #pragma unroll
        for (int i = 0; i < 2; i++) {
            uint32_t ro = (i * 16 + arow) * KP1E + kk + akof;
            ldm_x4(ah[i], sb + ro * 2);
            ldm_x4(al[i], sb + SM1_AL + ro * 2);
        }
        #pragma unroll
        for (int j = 0; j < 4; j++) {
            uint32_t ro = (n_w + j * 8 + brow) * KP1E + kk + bkof;
            ldm_x2(bh[j], sb + SM1_BH + ro * 2);
            ldm_x2(bl[j], sb + SM1_BL + ro * 2);
        }
        #pragma unroll
        for (int i = 0; i < 2; i++)
            #pragma unroll
            for (int j = 0; j < 4; j++) {
                mma16816(acc[i][j], ah[i], bh[j]);
                mma16816(acc[i][j], ah[i], bl[j]);
                mma16816(acc[i][j], al[i], bh[j]);
            }
    }

    #pragma unroll
    for (int i = 0; i < 2; i++) {
        int row = rb + i * 16 + (lane >> 2);
        #pragma unroll
        for (int j = 0; j < 4; j++) {
            int col = n0 + n_w + j * 8 + (lane & 3) * 2;
            float bb0 = (col     < MH_) ? __ldg(b1 + col)     : 0.0f;
            float bb1 = (col + 1 < MH_) ? __ldg(b1 + col + 1) : 0.0f;
            float f0 = fmaxf(acc[i][j][0] + bb0, 0.0f);
            float f1 = fmaxf(acc[i][j][1] + bb1, 0.0f);
            float f2 = fmaxf(acc[i][j][2] + bb0, 0.0f);
            float f3 = fmaxf(acc[i][j][3] + bb1, 0.0f);
            if (col >= MH_) f0 = f1 = f2 = f3 = 0.0f;
            unsigned short h0, l0, h1, l1;
            splitbf(f0, h0, l0); splitbf(f1, h1, l1);
            *(uint32_t*)(g_Hs_hi + row * MHP + col) = (uint32_t)h0 | ((uint32_t)h1 << 16);
            *(uint32_t*)(g_Hs_lo + row * MHP + col) = (uint32_t)l0 | ((uint32_t)l1 << 16);
            splitbf(f2, h0, l0); splitbf(f3, h1, l1);
            *(uint32_t*)(g_Hs_hi + (row + 8) * MHP + col) = (uint32_t)h0 | ((uint32_t)h1 << 16);
            *(uint32_t*)(g_Hs_lo + (row + 8) * MHP + col) = (uint32_t)l0 | ((uint32_t)l1 << 16);
        }
    }
}

// ---------------------------------------------------------------------------
// K2 (HMMA): unchanged, passing. M64/N64, K-split 2.
// ---------------------------------------------------------------------------
#define SM2_AL (64 * KP2E * 2)
#define SM2_BH (2 * SM2_AL)
#define SM2_BL (SM2_BH + 64 * KP2E * 2)
#define SMEM2  (SM2_BL + 64 * KP2E * 2)

__global__ void __launch_bounds__(128) k2_mma(const float* __restrict__ b2) {
    extern __shared__ char dsm[];
    const uint32_t sb = smem_u32(dsm);
    const int tid = threadIdx.x;
    const int lane = tid & 31, wid = tid >> 5;
    const int rb = blockIdx.x * 64;
    const int n0 = blockIdx.y * 64;
    const int kz = blockIdx.z;
    const int n_w = wid * 16;

    float acc[4][2][4];
    #pragma unroll
    for (int i = 0; i < 4; i++)
        #pragma unroll
        for (int j = 0; j < 2; j++)
            #pragma unroll
            for (int q = 0; q < 4; q++) acc[i][j][q] = 0.0f;

    const uint32_t arow = lane & 15;
    const uint32_t akof = (lane >> 4) << 3;
    const uint32_t brow = lane & 7;
    const uint32_t bkof = ((lane >> 3) & 1) << 3;

    #pragma unroll
    for (int ch = 0; ch < 2; ch++) {
        const int kb = kz * 512 + ch * 256;
        if (ch) __syncthreads();

        #pragma unroll
        for (int i = 0; i < 16; i++) {
            int idx = tid + i * 128;
            int r = idx >> 5, c = idx & 31;
            uint4 vh = *(const uint4*)(g_Hs_hi + (rb + r) * MHP + kb + c * 8);
            uint4 vl = *(const uint4*)(g_Hs_lo + (rb + r) * MHP + kb + c * 8);
            *(uint4*)(dsm + (r * KP2E + c * 8) * 2)          = vh;
            *(uint4*)(dsm + SM2_AL + (r * KP2E + c * 8) * 2) = vl;
        }
        #pragma unroll
        for (int i = 0; i < 16; i++) {
            int idx = tid + i * 128;
            int n = idx >> 5, c = idx & 31;
            uint4 vh = *(const uint4*)(g_W2h + (n0 + n) * MHP + kb + c * 8);
            uint4 vl = *(const uint4*)(g_W2l + (n0 + n) * MHP + kb + c * 8);
            *(uint4*)(dsm + SM2_BH + (n * KP2E + c * 8) * 2) = vh;
            *(uint4*)(dsm + SM2_BL + (n * KP2E + c * 8) * 2) = vl;
        }
        __syncthreads();

        #pragma unroll 2
        for (int ks = 0; ks < 16; ks++) {
            const uint32_t kk = ks * 16;
            uint32_t ah[4][4], al[4][4], bh[2][2], bl[2][2];
            #pragma unroll
            for (int i = 0; i < 4; i++) {
                uint32_t ro = (i * 16 + arow) * KP2E + kk + akof;
                ldm_x4(ah[i], sb + ro * 2);
                ldm_x4(al[i], sb + SM2_AL + ro * 2);
            }
            #pragma unroll
            for (int j = 0; j < 2; j++) {
                uint32_t ro = (n_w + j * 8 + brow) * KP2E + kk + bkof;
                ldm_x2(bh[j], sb + SM2_BH + ro * 2);
                ldm_x2(bl[j], sb + SM2_BL + ro * 2);
            }
            #pragma unroll
            for (int i = 0; i < 4; i++)
                #pragma unroll
                for (int j = 0; j < 2; j++) {
                    mma16816(acc[i][j], ah[i], bh[j]);
                    mma16816(acc[i][j], ah[i], bl[j]);
                    mma16816(acc[i][j], al[i], bh[j]);
                }
        }
    }

    float* dst = g_ENT2[kz];
    #pragma unroll
    for (int i = 0; i < 4; i++) {
        int row = rb + i * 16 + (lane >> 2);
        #pragma unroll
        for (int j = 0; j < 2; j++) {
            int col = n0 + n_w + j * 8 + (lane & 3) * 2;
            float bb0 = 0.f, bb1 = 0.f;
            if (kz == 0) { bb0 = __ldg(b2 + col); bb1 = __ldg(b2 + col + 1); }
            float2 o0 = make_float2(acc[i][j][0] + bb0, acc[i][j][1] + bb1);
            float2 o1 = make_float2(acc[i][j][2] + bb0, acc[i][j][3] + bb1);
            *(float2*)(dst + row * H_ + col)       = o0;
            *(float2*)(dst + (row + 8) * H_ + col) = o1;
        }
    }
}

// ---------------------------------------------------------------------------
// K3a gather: out[b,s,:] = word_embedding[ids[b,s]]  -- NO mask/ENT deps,
// runs on a forked stream CONCURRENTLY with the MLP chain.
// 4 rows per block -> 4096 blocks x 192 threads, streaming stores.
// ---------------------------------------------------------------------------
__global__ void __launch_bounds__(192) k3_gather(const int*   __restrict__ ids,
                                                 const float* __restrict__ we,
                                                 float*       __restrict__ out) {
    const int q    = blockIdx.x;
    const int row0 = (q >> 7) * S_ + ((q & 127) << 2);
    const int tid  = threadIdx.x;

    int id0 = __ldg(ids + row0 + 0);
    int id1 = __ldg(ids + row0 + 1);
    int id2 = __ldg(ids + row0 + 2);
    int id3 = __ldg(ids + row0 + 3);

    const float4* __restrict__ we4 = (const float4*)we;
    float4 v0 = we4[(long long)id0 * (H_ / 4) + tid];
    float4 v1 = we4[(long long)id1 * (H_ / 4) + tid];
    float4 v2 = we4[(long long)id2 * (H_ / 4) + tid];
    float4 v3 = we4[(long long)id3 * (H_ / 4) + tid];

    float4* __restrict__ out4 = (float4*)out;
    __stcs(out4 + (long long)(row0 + 0) * (H_ / 4) + tid, v0);
    __stcs(out4 + (long long)(row0 + 1) * (H_ / 4) + tid, v1);
    __stcs(out4 + (long long)(row0 + 2) * (H_ / 4) + tid, v2);
    __stcs(out4 + (long long)(row0 + 3) * (H_ / 4) + tid, v3);
}

// ---------------------------------------------------------------------------
// K3b fixup: out[row] += sum_e mask[b,e,s] * ENT[b*E+e]  (RMW, flagged rows
// only; ~52% of quads exit immediately, ~15% of rows touched).
// Runs after BOTH k2 (ENT2) and k3_gather (out rows).
// ---------------------------------------------------------------------------
__global__ void __launch_bounds__(192) k3_fixup(const float* __restrict__ mask,
                                                float*       __restrict__ out) {
    const int q    = blockIdx.x;
    const int b    = q >> 7;
    const int s0   = (q & 127) << 2;
    const int row0 = b * S_ + s0;
    const int tid  = threadIdx.x;
    const int lane = tid & 31;

    // Per-warp mask handling: lane -> (e = lane>>2, rr = lane&3).
    const float mval = __ldg(mask + (b * E_ + (lane >> 2)) * S_ + s0 + (lane & 3));
    const unsigned flag = __ballot_sync(0xffffffffu, mval != 0.0f);
    if (!flag) return;

    unsigned rowbits = flag | (flag >> 4);
    rowbits |= rowbits >> 8;
    rowbits |= rowbits >> 16;
    rowbits &= 0xFu;

    float4* __restrict__ out4 = (float4*)out;
    float4 v0, v1, v2, v3;
    if (rowbits & 1u) v0 = out4[(long long)(row0 + 0) * (H_ / 4) + tid];
    if (rowbits & 2u) v1 = out4[(long long)(row0 + 1) * (H_ / 4) + tid];
    if (rowbits & 4u) v2 = out4[(long long)(row0 + 2) * (H_ / 4) + tid];
    if (rowbits & 8u) v3 = out4[(long long)(row0 + 3) * (H_ / 4) + tid];

    #pragma unroll
    for (int e = 0; e < E_; e++) {
        const unsigned f4 = (flag >> (e * 4)) & 0xFu;
        if (f4) {
            const int idx = (b * E_ + e) * (H_ / 4) + tid;
            float4 p  = ((const float4*)g_ENT2[0])[idx];
            float4 p1 = ((const float4*)g_ENT2[1])[idx];
            p.x += p1.x; p.y += p1.y; p.z += p1.z; p.w += p1.w;
            const float m0 = __shfl_sync(0xffffffffu, mval, e * 4 + 0);
            const float m1 = __shfl_sync(0xffffffffu, mval, e * 4 + 1);
            const float m2 = __shfl_sync(0xffffffffu, mval, e * 4 + 2);
            const float m3 = __shfl_sync(0xffffffffu, mval, e * 4 + 3);
            if (f4 & 1u) {
                v0.x = fmaf(m0, p.x, v0.x); v0.y = fmaf(m0, p.y, v0.y);
                v0.z = fmaf(m0, p.z, v0.z); v0.w = fmaf(m0, p.w, v0.w); }
            if (f4 & 2u) {
                v1.x = fmaf(m1, p.x, v1.x); v1.y = fmaf(m1, p.y, v1.y);
                v1.z = fmaf(m1, p.z, v1.z); v1.w = fmaf(m1, p.w, v1.w); }
            if (f4 & 4u) {
                v2.x = fmaf(m2, p.x, v2.x); v2.y = fmaf(m2, p.y, v2.y);
                v2.z = fmaf(m2, p.z, v2.z); v2.w = fmaf(m2, p.w, v2.w); }
            if (f4 & 8u) {
                v3.x = fmaf(m3, p.x, v3.x); v3.y = fmaf(m3, p.y, v3.y);
                v3.z = fmaf(m3, p.z, v3.z); v3.w = fmaf(m3, p.w, v3.w); }
        }
    }

    if (rowbits & 1u) __stcs(out4 + (long long)(row0 + 0) * (H_ / 4) + tid, v0);
    if (rowbits & 2u) __stcs(out4 + (long long)(row0 + 1) * (H_ / 4) + tid, v1);
    if (rowbits & 4u) __stcs(out4 + (long long)(row0 + 2) * (H_ / 4) + tid, v2);
    if (rowbits & 8u) __stcs(out4 + (long long)(row0 + 3) * (H_ / 4) + tid, v3);
}

// ---------------------------------------------------------------------------
// Launch: fork the gather onto a second stream so it overlaps the MLP chain.
//   default: kprep -> k1 -> k2 ---------------------\
//   s2:      (wait evA) k3_gather (record evB) ------+--> fixup (waits evB)
// Stream/events created per call and intentionally NOT destroyed (destroying
// a forked stream mid-capture invalidates the capture; kernel_launch runs
// only a few times, host-side handles only, zero device allocation).
// ---------------------------------------------------------------------------
extern "C" void kernel_launch(void* const* d_in, const int* in_sizes, int n_in,
                              void* d_out, int out_size) {
    const int*   ids  = (const int*)  d_in[0];
    const float* X    = (const float*)d_in[1];
    const float* msk  = (const float*)d_in[2];
    const float* we   = (const float*)d_in[3];
    const float* W1   = (const float*)d_in[4];
    const float* b1   = (const float*)d_in[5];
    const float* W2   = (const float*)d_in[6];
    const float* b2   = (const float*)d_in[7];
    float* out = (float*)d_out;

    cudaFuncSetAttribute(k1_mma, cudaFuncAttributeMaxDynamicSharedMemorySize, SMEM1);
    cudaFuncSetAttribute(k2_mma, cudaFuncAttributeMaxDynamicSharedMemorySize, SMEM2);

    cudaStream_t s2;
    cudaEvent_t evA, evB;
    cudaStreamCreateWithFlags(&s2, cudaStreamNonBlocking);
    cudaEventCreateWithFlags(&evA, cudaEventDisableTiming);
    cudaEventCreateWithFlags(&evB, cudaEventDisableTiming);

    // Fork: gather runs concurrently with the MLP chain.
    cudaEventRecord(evA, 0);
    cudaStreamWaitEvent(s2, evA, 0);
    k3_gather<<<4096, 192, 0, s2>>>(ids, we, out);
    cudaEventRecord(evB, s2);

    // MLP chain on the default stream.
    kprep<<<928, dim3(32, 8)>>>(W2, W1, X);
    k1_mma<<<dim3(8, 8), 128, SMEM1>>>(b1);
    k2_mma<<<dim3(4, 12, 2), 128, SMEM2>>>(b2);

    // Join: fixup needs both ENT (k2, stream order) and gathered rows (evB).
    cudaStreamWaitEvent(0, evB, 0);
    k3_fixup<<<4096, 192>>>(msk, out);
}

// round 14
// speedup vs baseline: 1.2295x; 1.2295x over previous
#include <cuda_runtime.h>
#include <cuda_bf16.h>
#include <cstdint>

#define B_   32
#define S_   512
#define E_   8
#define H_   768
#define KG_  100
#define MH_  1000
#define NROW 256
#define MHP  1024            /* padded hidden */
#define K1P  128             /* k1 K padded  */
#define KP1E 136             /* k1 smem pitch (elements), 272B: conflict-free */
#define KPE2 136             /* k2 smem pitch for 128-k chunks */

// Scratch (device globals — no allocation allowed)
__device__ __align__(16) __nv_bfloat16 g_Xh[NROW * K1P];
__device__ __align__(16) __nv_bfloat16 g_Xl[NROW * K1P];
__device__ __align__(16) __nv_bfloat16 g_W1h[MHP * K1P];   // [n][k]
__device__ __align__(16) __nv_bfloat16 g_W1l[MHP * K1P];
__device__ __align__(16) __nv_bfloat16 g_W2h[H_ * MHP];    // [n][k]
__device__ __align__(16) __nv_bfloat16 g_W2l[H_ * MHP];
__device__ __align__(16) __nv_bfloat16 g_Hs_hi[NROW * MHP];
__device__ __align__(16) __nv_bfloat16 g_Hs_lo[NROW * MHP];
__device__ __align__(16) float g_ENT4[4][NROW * H_];

// ---------------- helpers ---------------------------------------------------
__device__ __forceinline__ uint32_t smem_u32(const void* p) {
    uint32_t a;
    asm("{ .reg .u64 t; cvta.to.shared.u64 t, %1; cvt.u32.u64 %0, t; }"
        : "=r"(a) : "l"(p));
    return a;
}
__device__ __forceinline__ void splitbf(float x, unsigned short& h,
                                        unsigned short& l) {
    __nv_bfloat16 hb = __float2bfloat16(x);
    float r = x - __bfloat162float(hb);
    __nv_bfloat16 lb = __float2bfloat16(r);
    h = *(unsigned short*)&hb;
    l = *(unsigned short*)&lb;
}
__device__ __forceinline__ void ldm_x4(uint32_t* r, uint32_t addr) {
    asm volatile("ldmatrix.sync.aligned.m8n8.x4.shared.b16 {%0,%1,%2,%3}, [%4];"
                 : "=r"(r[0]), "=r"(r[1]), "=r"(r[2]), "=r"(r[3]) : "r"(addr));
}
__device__ __forceinline__ void ldm_x2(uint32_t* r, uint32_t addr) {
    asm volatile("ldmatrix.sync.aligned.m8n8.x2.shared.b16 {%0,%1}, [%2];"
                 : "=r"(r[0]), "=r"(r[1]) : "r"(addr));
}
__device__ __forceinline__ void mma16816(float* c, const uint32_t* a,
                                         const uint32_t* b) {
    asm volatile(
        "mma.sync.aligned.m16n8k16.row.col.f32.bf16.bf16.f32 "
        "{%0,%1,%2,%3}, {%4,%5,%6,%7}, {%8,%9}, {%0,%1,%2,%3};"
        : "+f"(c[0]), "+f"(c[1]), "+f"(c[2]), "+f"(c[3])
        : "r"(a[0]), "r"(a[1]), "r"(a[2]), "r"(a[3]), "r"(b[0]), "r"(b[1]));
}

// ---------------------------------------------------------------------------
// kprep: split EVERYTHING once.  (unchanged, passing)
// ---------------------------------------------------------------------------
__global__ void __launch_bounds__(256) kprep(const float* __restrict__ W2,
                                             const float* __restrict__ W1,
                                             const float* __restrict__ X) {
    __shared__ unsigned short sh[32][33], sl[32][33];
    const int bid = blockIdx.x;
    const int tx = threadIdx.x, ty = threadIdx.y;

    if (bid < 768) {
        const int k0 = (bid & 31) * 32, n0 = (bid >> 5) * 32;
        #pragma unroll
        for (int j = 0; j < 4; j++) {
            int k = k0 + ty + j * 8;
            float v = (k < MH_) ? __ldg(W2 + (long long)k * H_ + n0 + tx) : 0.0f;
            unsigned short h, l; splitbf(v, h, l);
            sh[ty + j * 8][tx] = h; sl[ty + j * 8][tx] = l;
        }
        __syncthreads();
        #pragma unroll
        for (int j = 0; j < 4; j++) {
            int nn = ty + j * 8;
            g_W2h[(n0 + nn) * MHP + k0 + tx] = *(__nv_bfloat16*)&sh[tx][nn];
            g_W2l[(n0 + nn) * MHP + k0 + tx] = *(__nv_bfloat16*)&sl[tx][nn];
        }
    } else if (bid < 896) {
        const int t = bid - 768;
        const int k0 = (t & 3) * 32, n0 = (t >> 2) * 32;
        #pragma unroll
        for (int j = 0; j < 4; j++) {
            int k = k0 + ty + j * 8;
            float v = (k < KG_ && (n0 + tx) < MH_) ? __ldg(W1 + k * MH_ + n0 + tx)
                                                   : 0.0f;
            unsigned short h, l; splitbf(v, h, l);
            sh[ty + j * 8][tx] = h; sl[ty + j * 8][tx] = l;
        }
        __syncthreads();
        #pragma unroll
        for (int j = 0; j < 4; j++) {
            int nn = ty + j * 8;
            g_W1h[(n0 + nn) * K1P + k0 + tx] = *(__nv_bfloat16*)&sh[tx][nn];
            g_W1l[(n0 + nn) * K1P + k0 + tx] = *(__nv_bfloat16*)&sl[tx][nn];
        }
    } else {
        const int t = bid - 896;
        const int r0 = (t >> 2) * 32, k0 = (t & 3) * 32;
        #pragma unroll
        for (int j = 0; j < 4; j++) {
            int r = r0 + ty + j * 8, k = k0 + tx;
            float v = (k < KG_) ? __ldg(X + r * KG_ + k) : 0.0f;
            unsigned short h, l; splitbf(v, h, l);
            g_Xh[r * K1P + k] = *(__nv_bfloat16*)&h;
            g_Xl[r * K1P + k] = *(__nv_bfloat16*)&l;
        }
    }
}

// ---------------------------------------------------------------------------
// K1 (HMMA): unchanged, passing.
// ---------------------------------------------------------------------------
#define SM1_AL (32 * KP1E * 2)
#define SM1_BH (2 * SM1_AL)
#define SM1_BL (SM1_BH + 128 * KP1E * 2)
#define SMEM1  (SM1_BL + 128 * KP1E * 2)

__global__ void __launch_bounds__(128) k1_mma(const float* __restrict__ b1) {
    extern __shared__ char dsm[];
    const uint32_t sb = smem_u32(dsm);
    const int tid = threadIdx.x;
    const int lane = tid & 31, wid = tid >> 5;
    const int rb = blockIdx.x * 32;
    const int n0 = blockIdx.y * 128;

    #pragma unroll
    for (int i = 0; i < 4; i++) {
        int idx = tid + i * 128;
        int r = idx >> 4, c = idx & 15;
        uint4 vh = *(const uint4*)(g_Xh + (rb + r) * K1P + c * 8);
        uint4 vl = *(const uint4*)(g_Xl + (rb + r) * K1P + c * 8);
        *(uint4*)(dsm + (r * KP1E + c * 8) * 2)          = vh;
        *(uint4*)(dsm + SM1_AL + (r * KP1E + c * 8) * 2) = vl;
    }
    #pragma unroll
    for (int i = 0; i < 16; i++) {
        int idx = tid + i * 128;
        int n = idx >> 4, c = idx & 15;
        uint4 vh = *(const uint4*)(g_W1h + (n0 + n) * K1P + c * 8);
        uint4 vl = *(const uint4*)(g_W1l + (n0 + n) * K1P + c * 8);
        *(uint4*)(dsm + SM1_BH + (n * KP1E + c * 8) * 2) = vh;
        *(uint4*)(dsm + SM1_BL + (n * KP1E + c * 8) * 2) = vl;
    }
    __syncthreads();

    const int n_w = wid * 32;
    float acc[2][4][4];
    #pragma unroll
    for (int i = 0; i < 2; i++)
        #pragma unroll
        for (int j = 0; j < 4; j++)
            #pragma unroll
            for (int q = 0; q < 4; q++) acc[i][j][q] = 0.0f;

    const uint32_t arow = lane & 15;
    const uint32_t akof = (lane >> 4) << 3;
    const uint32_t brow = lane & 7;
    const uint32_t bkof = ((lane >> 3) & 1) << 3;

    #pragma unroll
    for (int ks = 0; ks < 8; ks++) {
        const uint32_t kk = ks * 16;
        uint32_t ah[2][4], al[2][4], bh[4][2], bl[4][2];
        #pragma unroll
        for (int i = 0; i < 2; i++) {
            uint32_t ro = (i * 16 + arow) * KP1E + kk + akof;
            ldm_x4(ah[i], sb + ro * 2);
            ldm_x4(al[i], sb + SM1_AL + ro * 2);
        }
        #pragma unroll
        for (int j = 0; j < 4; j++) {
            uint32_t ro = (n_w + j * 8 + brow) * KP1E + kk + bkof;
            ldm_x2(bh[j], sb + SM1_BH + ro * 2);
            ldm_x2(bl[j], sb + SM1_BL + ro * 2);
        }
        #pragma unroll
        for (int i = 0; i < 2; i++)
            #pragma unroll
            for (int j = 0; j < 4; j++) {
                mma16816(acc[i][j], ah[i], bh[j]);
                mma16816(acc[i][j], ah[i], bl[j]);
                mma16816(acc[i][j], al[i], bh[j]);
            }
    }

    #pragma unroll
    for (int i = 0; i < 2; i++) {
        int row = rb + i * 16 + (lane >> 2);
        #pragma unroll
        for (int j = 0; j < 4; j++) {
            int col = n0 + n_w + j * 8 + (lane & 3) * 2;
            float bb0 = (col     < MH_) ? __ldg(b1 + col)     : 0.0f;
            float bb1 = (col + 1 < MH_) ? __ldg(b1 + col + 1) : 0.0f;
            float f0 = fmaxf(acc[i][j][0] + bb0, 0.0f);
            float f1 = fmaxf(acc[i][j][1] + bb1, 0.0f);
            float f2 = fmaxf(acc[i][j][2] + bb0, 0.0f);
            float f3 = fmaxf(acc[i][j][3] + bb1, 0.0f);
            if (col >= MH_) f0 = f1 = f2 = f3 = 0.0f;
            unsigned short h0, l0, h1, l1;
            splitbf(f0, h0, l0); splitbf(f1, h1, l1);
            *(uint32_t*)(g_Hs_hi + row * MHP + col) = (uint32_t)h0 | ((uint32_t)h1 << 16);
            *(uint32_t*)(g_Hs_lo + row * MHP + col) = (uint32_t)l0 | ((uint32_t)l1 << 16);
            splitbf(f2, h0, l0); splitbf(f3, h1, l1);
            *(uint32_t*)(g_Hs_hi + (row + 8) * MHP + col) = (uint32_t)h0 | ((uint32_t)h1 << 16);
            *(uint32_t*)(g_Hs_lo + (row + 8) * MHP + col) = (uint32_t)l0 | ((uint32_t)l1 << 16);
        }
    }
}

// ---------------------------------------------------------------------------
// K2 v3 (HMMA): ENT_part[kz] = Hs @ W2T (+ b2 on kz==0)
// grid (8, 12, 4) = 384 blocks (~2.6/SM). M tile 32, N tile 64, kz covers
// 256 k in 2 chunks of 128. smem 52 KB -> multiple blocks/SM co-resident.
// block 128 (4 warps, N-slice 16 each). acc = 16 regs -> no spills.
// ---------------------------------------------------------------------------
#define SM2_AL (32 * KPE2 * 2)            /* 8704  */
#define SM2_BH (2 * SM2_AL)               /* 17408 */
#define SM2_BL (SM2_BH + 64 * KPE2 * 2)   /* 34816 */
#define SMEM2  (SM2_BL + 64 * KPE2 * 2)   /* 52224 */

__global__ void __launch_bounds__(128) k2_mma(const float* __restrict__ b2) {
    extern __shared__ char dsm[];
    const uint32_t sb = smem_u32(dsm);
    const int tid = threadIdx.x;
    const int lane = tid & 31, wid = tid >> 5;
    const int rb = blockIdx.x * 32;
    const int n0 = blockIdx.y * 64;
    const int kz = blockIdx.z;
    const int n_w = wid * 16;

    float acc[2][2][4];
    #pragma unroll
    for (int i = 0; i < 2; i++)
        #pragma unroll
        for (int j = 0; j < 2; j++)
            #pragma unroll
            for (int q = 0; q < 4; q++) acc[i][j][q] = 0.0f;

    const uint32_t arow = lane & 15;
    const uint32_t akof = (lane >> 4) << 3;
    const uint32_t brow = lane & 7;
    const uint32_t bkof = ((lane >> 3) & 1) << 3;

    #pragma unroll
    for (int ch = 0; ch < 2; ch++) {
        const int kb = kz * 256 + ch * 128;
        if (ch) __syncthreads();

        // Stage A (hi/lo): 32 rows x 16 uint4
        #pragma unroll
        for (int i = 0; i < 4; i++) {
            int idx = tid + i * 128;
            int r = idx >> 4, c = idx & 15;
            uint4 vh = *(const uint4*)(g_Hs_hi + (rb + r) * MHP + kb + c * 8);
            uint4 vl = *(const uint4*)(g_Hs_lo + (rb + r) * MHP + kb + c * 8);
            *(uint4*)(dsm + (r * KPE2 + c * 8) * 2)          = vh;
            *(uint4*)(dsm + SM2_AL + (r * KPE2 + c * 8) * 2) = vl;
        }
        // Stage B (hi/lo): 64 rows x 16 uint4
        #pragma unroll
        for (int i = 0; i < 8; i++) {
            int idx = tid + i * 128;
            int n = idx >> 4, c = idx & 15;
            uint4 vh = *(const uint4*)(g_W2h + (n0 + n) * MHP + kb + c * 8);
            uint4 vl = *(const uint4*)(g_W2l + (n0 + n) * MHP + kb + c * 8);
            *(uint4*)(dsm + SM2_BH + (n * KPE2 + c * 8) * 2) = vh;
            *(uint4*)(dsm + SM2_BL + (n * KPE2 + c * 8) * 2) = vl;
        }
        __syncthreads();

        #pragma unroll
        for (int ks = 0; ks < 8; ks++) {
            const uint32_t kk = ks * 16;
            uint32_t ah[2][4], al[2][4], bh[2][2], bl[2][2];
            #pragma unroll
            for (int i = 0; i < 2; i++) {
                uint32_t ro = (i * 16 + arow) * KPE2 + kk + akof;
                ldm_x4(ah[i], sb + ro * 2);
                ldm_x4(al[i], sb + SM2_AL + ro * 2);
            }
            #pragma unroll
            for (int j = 0; j < 2; j++) {
                uint32_t ro = (n_w + j * 8 + brow) * KPE2 + kk + bkof;
                ldm_x2(bh[j], sb + SM2_BH + ro * 2);
                ldm_x2(bl[j], sb + SM2_BL + ro * 2);
            }
            #pragma unroll
            for (int i = 0; i < 2; i++)
                #pragma unroll
                for (int j = 0; j < 2; j++) {
                    mma16816(acc[i][j], ah[i], bh[j]);
                    mma16816(acc[i][j], ah[i], bl[j]);
                    mma16816(acc[i][j], al[i], bh[j]);
                }
        }
    }

    float* dst = g_ENT4[kz];
    #pragma unroll
    for (int i = 0; i < 2; i++) {
        int row = rb + i * 16 + (lane >> 2);
        #pragma unroll
        for (int j = 0; j < 2; j++) {
            int col = n0 + n_w + j * 8 + (lane & 3) * 2;
            float bb0 = 0.f, bb1 = 0.f;
            if (kz == 0) { bb0 = __ldg(b2 + col); bb1 = __ldg(b2 + col + 1); }
            float2 o0 = make_float2(acc[i][j][0] + bb0, acc[i][j][1] + bb1);
            float2 o1 = make_float2(acc[i][j][2] + bb0, acc[i][j][3] + bb1);
            *(float2*)(dst + row * H_ + col)       = o0;
            *(float2*)(dst + (row + 8) * H_ + col) = o1;
        }
    }
}

// ---------------------------------------------------------------------------
// K3: round-11 form (measured 15.2us) summing 4 ENT partials inline.
// 4 rows per block -> 4096 blocks x 192 threads. Per-warp masks, no barrier,
// streaming output stores.
// ---------------------------------------------------------------------------
__global__ void __launch_bounds__(192) k3_fuse(const int*   __restrict__ ids,
                                               const float* __restrict__ mask,
                                               const float* __restrict__ we,
                                               float*       __restrict__ out) {
    const int rblk = blockIdx.x;          // 4096
    const int b    = rblk >> 7;
    const int s0   = (rblk & 127) << 2;
    const int row0 = b * S_ + s0;
    const int tid  = threadIdx.x;
    const int lane = tid & 31;

    int wid0 = __ldg(ids + row0 + 0);
    int wid1 = __ldg(ids + row0 + 1);
    int wid2 = __ldg(ids + row0 + 2);
    int wid3 = __ldg(ids + row0 + 3);

    const float4* __restrict__ we4 = (const float4*)we;
    float4 v0 = we4[(long long)wid0 * (H_ / 4) + tid];
    float4 v1 = we4[(long long)wid1 * (H_ / 4) + tid];
    float4 v2 = we4[(long long)wid2 * (H_ / 4) + tid];
    float4 v3 = we4[(long long)wid3 * (H_ / 4) + tid];

    const float mval = __ldg(mask + (b * E_ + (lane >> 2)) * S_ + s0 + (lane & 3));
    const unsigned flag = __ballot_sync(0xffffffffu, mval != 0.0f);

    if (flag) {
        #pragma unroll
        for (int e = 0; e < E_; e++) {
            const unsigned f4 = (flag >> (e * 4)) & 0xFu;
            if (f4) {
                const int idx = (b * E_ + e) * (H_ / 4) + tid;
                float4 p  = ((const float4*)g_ENT4[0])[idx];
                float4 p1 = ((const float4*)g_ENT4[1])[idx];
                float4 p2 = ((const float4*)g_ENT4[2])[idx];
                float4 p3 = ((const float4*)g_ENT4[3])[idx];
                p.x += p1.x + p2.x + p3.x;
                p.y += p1.y + p2.y + p3.y;
                p.z += p1.z + p2.z + p3.z;
                p.w += p1.w + p2.w + p3.w;
                const float m0 = __shfl_sync(0xffffffffu, mval, e * 4 + 0);
                const float m1 = __shfl_sync(0xffffffffu, mval, e * 4 + 1);
                const float m2 = __shfl_sync(0xffffffffu, mval, e * 4 + 2);
                const float m3 = __shfl_sync(0xffffffffu, mval, e * 4 + 3);
                if (f4 & 1u) {
                    v0.x = fmaf(m0, p.x, v0.x); v0.y = fmaf(m0, p.y, v0.y);
                    v0.z = fmaf(m0, p.z, v0.z); v0.w = fmaf(m0, p.w, v0.w); }
                if (f4 & 2u) {
                    v1.x = fmaf(m1, p.x, v1.x); v1.y = fmaf(m1, p.y, v1.y);
                    v1.z = fmaf(m1, p.z, v1.z); v1.w = fmaf(m1, p.w, v1.w); }
                if (f4 & 4u) {
                    v2.x = fmaf(m2, p.x, v2.x); v2.y = fmaf(m2, p.y, v2.y);
                    v2.z = fmaf(m2, p.z, v2.z); v2.w = fmaf(m2, p.w, v2.w); }
                if (f4 & 8u) {
                    v3.x = fmaf(m3, p.x, v3.x); v3.y = fmaf(m3, p.y, v3.y);
                    v3.z = fmaf(m3, p.z, v3.z); v3.w = fmaf(m3, p.w, v3.w); }
            }
        }
    }

    float4* __restrict__ out4 = (float4*)out;
    __stcs(out4 + (long long)(row0 + 0) * (H_ / 4) + tid, v0);
    __stcs(out4 + (long long)(row0 + 1) * (H_ / 4) + tid, v1);
    __stcs(out4 + (long long)(row0 + 2) * (H_ / 4) + tid, v2);
    __stcs(out4 + (long long)(row0 + 3) * (H_ / 4) + tid, v3);
}

// ---------------------------------------------------------------------------
extern "C" void kernel_launch(void* const* d_in, const int* in_sizes, int n_in,
                              void* d_out, int out_size) {
    const int*   ids  = (const int*)  d_in[0];
    const float* X    = (const float*)d_in[1];
    const float* msk  = (const float*)d_in[2];
    const float* we   = (const float*)d_in[3];
    const float* W1   = (const float*)d_in[4];
    const float* b1   = (const float*)d_in[5];
    const float* W2   = (const float*)d_in[6];
    const float* b2   = (const float*)d_in[7];
    float* out = (float*)d_out;

    cudaFuncSetAttribute(k1_mma, cudaFuncAttributeMaxDynamicSharedMemorySize, SMEM1);
    cudaFuncSetAttribute(k2_mma, cudaFuncAttributeMaxDynamicSharedMemorySize, SMEM2);

    kprep<<<928, dim3(32, 8)>>>(W2, W1, X);
    k1_mma<<<dim3(8, 8), 128, SMEM1>>>(b1);
    k2_mma<<<dim3(8, 12, 4), 128, SMEM2>>>(b2);
    k3_fuse<<<4096, 192>>>(ids, msk, we, out);
}

// round 15
// speedup vs baseline: 1.2308x; 1.0010x over previous
#include <cuda_runtime.h>
#include <cuda_bf16.h>
#include <cstdint>

#define B_   32
#define S_   512
#define E_   8
#define H_   768
#define KG_  100
#define MH_  1000
#define NROW 256
#define MHP  1024            /* padded hidden */
#define K1P  128             /* k1 K padded  */
#define KP1E 136             /* k1 smem pitch (elements), 272B: conflict-free */
#define KPE2 136             /* k2 smem pitch for 128-k chunks */

// Scratch (device globals — no allocation allowed)
__device__ __align__(16) __nv_bfloat16 g_Xh[NROW * K1P];
__device__ __align__(16) __nv_bfloat16 g_Xl[NROW * K1P];
__device__ __align__(16) __nv_bfloat16 g_W1h[MHP * K1P];   // [n][k]
__device__ __align__(16) __nv_bfloat16 g_W1l[MHP * K1P];
__device__ __align__(16) __nv_bfloat16 g_W2h[H_ * MHP];    // [n][k]
__device__ __align__(16) __nv_bfloat16 g_W2l[H_ * MHP];
__device__ __align__(16) __nv_bfloat16 g_Hs_hi[NROW * MHP];
__device__ __align__(16) __nv_bfloat16 g_Hs_lo[NROW * MHP];
__device__ __align__(16) float g_ENT4[4][NROW * H_];

// ---------------- helpers ---------------------------------------------------
__device__ __forceinline__ uint32_t smem_u32(const void* p) {
    uint32_t a;
    asm("{ .reg .u64 t; cvta.to.shared.u64 t, %1; cvt.u32.u64 %0, t; }"
        : "=r"(a) : "l"(p));
    return a;
}
__device__ __forceinline__ void splitbf(float x, unsigned short& h,
                                        unsigned short& l) {
    __nv_bfloat16 hb = __float2bfloat16(x);
    float r = x - __bfloat162float(hb);
    __nv_bfloat16 lb = __float2bfloat16(r);
    h = *(unsigned short*)&hb;
    l = *(unsigned short*)&lb;
}
__device__ __forceinline__ void ldm_x4(uint32_t* r, uint32_t addr) {
    asm volatile("ldmatrix.sync.aligned.m8n8.x4.shared.b16 {%0,%1,%2,%3}, [%4];"
                 : "=r"(r[0]), "=r"(r[1]), "=r"(r[2]), "=r"(r[3]) : "r"(addr));
}
__device__ __forceinline__ void ldm_x2(uint32_t* r, uint32_t addr) {
    asm volatile("ldmatrix.sync.aligned.m8n8.x2.shared.b16 {%0,%1}, [%2];"
                 : "=r"(r[0]), "=r"(r[1]) : "r"(addr));
}
__device__ __forceinline__ void mma16816(float* c, const uint32_t* a,
                                         const uint32_t* b) {
    asm volatile(
        "mma.sync.aligned.m16n8k16.row.col.f32.bf16.bf16.f32 "
        "{%0,%1,%2,%3}, {%4,%5,%6,%7}, {%8,%9}, {%0,%1,%2,%3};"
        : "+f"(c[0]), "+f"(c[1]), "+f"(c[2]), "+f"(c[3])
        : "r"(a[0]), "r"(a[1]), "r"(a[2]), "r"(a[3]), "r"(b[0]), "r"(b[1]));
}

// ---------------------------------------------------------------------------
// kprep: split EVERYTHING once.  (unchanged, passing)
// ---------------------------------------------------------------------------
__global__ void __launch_bounds__(256) kprep(const float* __restrict__ W2,
                                             const float* __restrict__ W1,
                                             const float* __restrict__ X) {
    __shared__ unsigned short sh[32][33], sl[32][33];
    const int bid = blockIdx.x;
    const int tx = threadIdx.x, ty = threadIdx.y;

    if (bid < 768) {
        const int k0 = (bid & 31) * 32, n0 = (bid >> 5) * 32;
        #pragma unroll
        for (int j = 0; j < 4; j++) {
            int k = k0 + ty + j * 8;
            float v = (k < MH_) ? __ldg(W2 + (long long)k * H_ + n0 + tx) : 0.0f;
            unsigned short h, l; splitbf(v, h, l);
            sh[ty + j * 8][tx] = h; sl[ty + j * 8][tx] = l;
        }
        __syncthreads();
        #pragma unroll
        for (int j = 0; j < 4; j++) {
            int nn = ty + j * 8;
            g_W2h[(n0 + nn) * MHP + k0 + tx] = *(__nv_bfloat16*)&sh[tx][nn];
            g_W2l[(n0 + nn) * MHP + k0 + tx] = *(__nv_bfloat16*)&sl[tx][nn];
        }
    } else if (bid < 896) {
        const int t = bid - 768;
        const int k0 = (t & 3) * 32, n0 = (t >> 2) * 32;
        #pragma unroll
        for (int j = 0; j < 4; j++) {
            int k = k0 + ty + j * 8;
            float v = (k < KG_ && (n0 + tx) < MH_) ? __ldg(W1 + k * MH_ + n0 + tx)
                                                   : 0.0f;
            unsigned short h, l; splitbf(v, h, l);
            sh[ty + j * 8][tx] = h; sl[ty + j * 8][tx] = l;
        }
        __syncthreads();
        #pragma unroll
        for (int j = 0; j < 4; j++) {
            int nn = ty + j * 8;
            g_W1h[(n0 + nn) * K1P + k0 + tx] = *(__nv_bfloat16*)&sh[tx][nn];
            g_W1l[(n0 + nn) * K1P + k0 + tx] = *(__nv_bfloat16*)&sl[tx][nn];
        }
    } else {
        const int t = bid - 896;
        const int r0 = (t >> 2) * 32, k0 = (t & 3) * 32;
        #pragma unroll
        for (int j = 0; j < 4; j++) {
            int r = r0 + ty + j * 8, k = k0 + tx;
            float v = (k < KG_) ? __ldg(X + r * KG_ + k) : 0.0f;
            unsigned short h, l; splitbf(v, h, l);
            g_Xh[r * K1P + k] = *(__nv_bfloat16*)&h;
            g_Xl[r * K1P + k] = *(__nv_bfloat16*)&l;
        }
    }
}

// ---------------------------------------------------------------------------
// K1 (HMMA): unchanged except early PDL trigger so k2 can begin staging W2.
// ---------------------------------------------------------------------------
#define SM1_AL (32 * KP1E * 2)
#define SM1_BH (2 * SM1_AL)
#define SM1_BL (SM1_BH + 128 * KP1E * 2)
#define SMEM1  (SM1_BL + 128 * KP1E * 2)

__global__ void __launch_bounds__(128) k1_mma(const float* __restrict__ b1) {
#if __CUDA_ARCH__ >= 900
    cudaTriggerProgrammaticLaunchCompletion();
#endif
    extern __shared__ char dsm[];
    const uint32_t sb = smem_u32(dsm);
    const int tid = threadIdx.x;
    const int lane = tid & 31, wid = tid >> 5;
    const int rb = blockIdx.x * 32;
    const int n0 = blockIdx.y * 128;

    #pragma unroll
    for (int i = 0; i < 4; i++) {
        int idx = tid + i * 128;
        int r = idx >> 4, c = idx & 15;
        uint4 vh = *(const uint4*)(g_Xh + (rb + r) * K1P + c * 8);
        uint4 vl = *(const uint4*)(g_Xl + (rb + r) * K1P + c * 8);
        *(uint4*)(dsm + (r * KP1E + c * 8) * 2)          = vh;
        *(uint4*)(dsm + SM1_AL + (r * KP1E + c * 8) * 2) = vl;
    }
    #pragma unroll
    for (int i = 0; i < 16; i++) {
        int idx = tid + i * 128;
        int n = idx >> 4, c = idx & 15;
        uint4 vh = *(const uint4*)(g_W1h + (n0 + n) * K1P + c * 8);
        uint4 vl = *(const uint4*)(g_W1l + (n0 + n) * K1P + c * 8);
        *(uint4*)(dsm + SM1_BH + (n * KP1E + c * 8) * 2) = vh;
        *(uint4*)(dsm + SM1_BL + (n * KP1E + c * 8) * 2) = vl;
    }
    __syncthreads();

    const int n_w = wid * 32;
    float acc[2][4][4];
    #pragma unroll
    for (int i = 0; i < 2; i++)
        #pragma unroll
        for (int j = 0; j < 4; j++)
            #pragma unroll
            for (int q = 0; q < 4; q++) acc[i][j][q] = 0.0f;

    const uint32_t arow = lane & 15;
    const uint32_t akof = (lane >> 4) << 3;
    const uint32_t brow = lane & 7;
    const uint32_t bkof = ((lane >> 3) & 1) << 3;

    #pragma unroll
    for (int ks = 0; ks < 8; ks++) {
        const uint32_t kk = ks * 16;
        uint32_t ah[2][4], al[2][4], bh[4][2], bl[4][2];
        #pragma unroll
        for (int i = 0; i < 2; i++) {
            uint32_t ro = (i * 16 + arow) * KP1E + kk + akof;
            ldm_x4(ah[i], sb + ro * 2);
            ldm_x4(al[i], sb + SM1_AL + ro * 2);
        }
        #pragma unroll
        for (int j = 0; j < 4; j++) {
            uint32_t ro = (n_w + j * 8 + brow) * KP1E + kk + bkof;
            ldm_x2(bh[j], sb + SM1_BH + ro * 2);
            ldm_x2(bl[j], sb + SM1_BL + ro * 2);
        }
        #pragma unroll
        for (int i = 0; i < 2; i++)
            #pragma unroll
            for (int j = 0; j < 4; j++) {
                mma16816(acc[i][j], ah[i], bh[j]);
                mma16816(acc[i][j], ah[i], bl[j]);
                mma16816(acc[i][j], al[i], bh[j]);
            }
    }

    #pragma unroll
    for (int i = 0; i < 2; i++) {
        int row = rb + i * 16 + (lane >> 2);
        #pragma unroll
        for (int j = 0; j < 4; j++) {
            int col = n0 + n_w + j * 8 + (lane & 3) * 2;
            float bb0 = (col     < MH_) ? __ldg(b1 + col)     : 0.0f;
            float bb1 = (col + 1 < MH_) ? __ldg(b1 + col + 1) : 0.0f;
            float f0 = fmaxf(acc[i][j][0] + bb0, 0.0f);
            float f1 = fmaxf(acc[i][j][1] + bb1, 0.0f);
            float f2 = fmaxf(acc[i][j][2] + bb0, 0.0f);
            float f3 = fmaxf(acc[i][j][3] + bb1, 0.0f);
            if (col >= MH_) f0 = f1 = f2 = f3 = 0.0f;
            unsigned short h0, l0, h1, l1;
            splitbf(f0, h0, l0); splitbf(f1, h1, l1);
            *(uint32_t*)(g_Hs_hi + row * MHP + col) = (uint32_t)h0 | ((uint32_t)h1 << 16);
            *(uint32_t*)(g_Hs_lo + row * MHP + col) = (uint32_t)l0 | ((uint32_t)l1 << 16);
            splitbf(f2, h0, l0); splitbf(f3, h1, l1);
            *(uint32_t*)(g_Hs_hi + (row + 8) * MHP + col) = (uint32_t)h0 | ((uint32_t)h1 << 16);
            *(uint32_t*)(g_Hs_lo + (row + 8) * MHP + col) = (uint32_t)l0 | ((uint32_t)l1 << 16);
        }
    }
}

// ---------------------------------------------------------------------------
// K2 v3 (HMMA): same math; PDL-aware. PSS secondary of k1: stages W2 first,
// grid-dep-syncs, then stages Hs. Triggers early so k3 can launch under it.
// grid (8,12,4) = 384 blocks (all resident in one wave at 52KB smem).
// ---------------------------------------------------------------------------
#define SM2_AL (32 * KPE2 * 2)            /* 8704  */
#define SM2_BH (2 * SM2_AL)               /* 17408 */
#define SM2_BL (SM2_BH + 64 * KPE2 * 2)   /* 34816 */
#define SMEM2  (SM2_BL + 64 * KPE2 * 2)   /* 52224 */

__global__ void __launch_bounds__(128) k2_mma(const float* __restrict__ b2) {
#if __CUDA_ARCH__ >= 900
    cudaTriggerProgrammaticLaunchCompletion();
#endif
    extern __shared__ char dsm[];
    const uint32_t sb = smem_u32(dsm);
    const int tid = threadIdx.x;
    const int lane = tid & 31, wid = tid >> 5;
    const int rb = blockIdx.x * 32;
    const int n0 = blockIdx.y * 64;
    const int kz = blockIdx.z;
    const int n_w = wid * 16;

    float acc[2][2][4];
    #pragma unroll
    for (int i = 0; i < 2; i++)
        #pragma unroll
        for (int j = 0; j < 2; j++)
            #pragma unroll
            for (int q = 0; q < 4; q++) acc[i][j][q] = 0.0f;

    const uint32_t arow = lane & 15;
    const uint32_t akof = (lane >> 4) << 3;
    const uint32_t brow = lane & 7;
    const uint32_t bkof = ((lane >> 3) & 1) << 3;

    #pragma unroll
    for (int ch = 0; ch < 2; ch++) {
        const int kb = kz * 256 + ch * 128;
        if (ch) __syncthreads();

        // Stage B (hi/lo) FIRST -- W2 splits come from kprep, not k1.
        #pragma unroll
        for (int i = 0; i < 8; i++) {
            int idx = tid + i * 128;
            int n = idx >> 4, c = idx & 15;
            uint4 vh = *(const uint4*)(g_W2h + (n0 + n) * MHP + kb + c * 8);
            uint4 vl = *(const uint4*)(g_W2l + (n0 + n) * MHP + kb + c * 8);
            *(uint4*)(dsm + SM2_BH + (n * KPE2 + c * 8) * 2) = vh;
            *(uint4*)(dsm + SM2_BL + (n * KPE2 + c * 8) * 2) = vl;
        }

#if __CUDA_ARCH__ >= 900
        if (ch == 0) cudaGridDependencySynchronize();  // wait for k1's Hs
#endif

        // Stage A (hi/lo): 32 rows x 16 uint4 (k1 output)
        #pragma unroll
        for (int i = 0; i < 4; i++) {
            int idx = tid + i * 128;
            int r = idx >> 4, c = idx & 15;
            uint4 vh = *(const uint4*)(g_Hs_hi + (rb + r) * MHP + kb + c * 8);
            uint4 vl = *(const uint4*)(g_Hs_lo + (rb + r) * MHP + kb + c * 8);
            *(uint4*)(dsm + (r * KPE2 + c * 8) * 2)          = vh;
            *(uint4*)(dsm + SM2_AL + (r * KPE2 + c * 8) * 2) = vl;
        }
        __syncthreads();

        #pragma unroll
        for (int ks = 0; ks < 8; ks++) {
            const uint32_t kk = ks * 16;
            uint32_t ah[2][4], al[2][4], bh[2][2], bl[2][2];
            #pragma unroll
            for (int i = 0; i < 2; i++) {
                uint32_t ro = (i * 16 + arow) * KPE2 + kk + akof;
                ldm_x4(ah[i], sb + ro * 2);
                ldm_x4(al[i], sb + SM2_AL + ro * 2);
            }
            #pragma unroll
            for (int j = 0; j < 2; j++) {
                uint32_t ro = (n_w + j * 8 + brow) * KPE2 + kk + bkof;
                ldm_x2(bh[j], sb + SM2_BH + ro * 2);
                ldm_x2(bl[j], sb + SM2_BL + ro * 2);
            }
            #pragma unroll
            for (int i = 0; i < 2; i++)
                #pragma unroll
                for (int j = 0; j < 2; j++) {
                    mma16816(acc[i][j], ah[i], bh[j]);
                    mma16816(acc[i][j], ah[i], bl[j]);
                    mma16816(acc[i][j], al[i], bh[j]);
                }
        }
    }

    float* dst = g_ENT4[kz];
    #pragma unroll
    for (int i = 0; i < 2; i++) {
        int row = rb + i * 16 + (lane >> 2);
        #pragma unroll
        for (int j = 0; j < 2; j++) {
            int col = n0 + n_w + j * 8 + (lane & 3) * 2;
            float bb0 = 0.f, bb1 = 0.f;
            if (kz == 0) { bb0 = __ldg(b2 + col); bb1 = __ldg(b2 + col + 1); }
            float2 o0 = make_float2(acc[i][j][0] + bb0, acc[i][j][1] + bb1);
            float2 o1 = make_float2(acc[i][j][2] + bb0, acc[i][j][3] + bb1);
            *(float2*)(dst + row * H_ + col)       = o0;
            *(float2*)(dst + (row + 8) * H_ + col) = o1;
        }
    }
}

// ---------------------------------------------------------------------------
// K3: PSS secondary of k2 -- its gathers run WHILE k2 computes. Only the
// flagged blocks (~48%) grid-dep-sync before touching ENT; the rest never
// wait. Body otherwise identical to the measured round-14 version.
// ---------------------------------------------------------------------------
__global__ void __launch_bounds__(192) k3_fuse(const int*   __restrict__ ids,
                                               const float* __restrict__ mask,
                                               const float* __restrict__ we,
                                               float*       __restrict__ out) {
    const int rblk = blockIdx.x;          // 4096
    const int b    = rblk >> 7;
    const int s0   = (rblk & 127) << 2;
    const int row0 = b * S_ + s0;
    const int tid  = threadIdx.x;
    const int lane = tid & 31;

    int wid0 = __ldg(ids + row0 + 0);
    int wid1 = __ldg(ids + row0 + 1);
    int wid2 = __ldg(ids + row0 + 2);
    int wid3 = __ldg(ids + row0 + 3);

    const float4* __restrict__ we4 = (const float4*)we;
    float4 v0 = we4[(long long)wid0 * (H_ / 4) + tid];
    float4 v1 = we4[(long long)wid1 * (H_ / 4) + tid];
    float4 v2 = we4[(long long)wid2 * (H_ / 4) + tid];
    float4 v3 = we4[(long long)wid3 * (H_ / 4) + tid];

    const float mval = __ldg(mask + (b * E_ + (lane >> 2)) * S_ + s0 + (lane & 3));
    const unsigned flag = __ballot_sync(0xffffffffu, mval != 0.0f);

    if (flag) {
#if __CUDA_ARCH__ >= 900
        cudaGridDependencySynchronize();   // block-uniform: wait for k2's ENT
#endif
        #pragma unroll
        for (int e = 0; e < E_; e++) {
            const unsigned f4 = (flag >> (e * 4)) & 0xFu;
            if (f4) {
                const int idx = (b * E_ + e) * (H_ / 4) + tid;
                float4 p  = ((const float4*)g_ENT4[0])[idx];
                float4 p1 = ((const float4*)g_ENT4[1])[idx];
                float4 p2 = ((const float4*)g_ENT4[2])[idx];
                float4 p3 = ((const float4*)g_ENT4[3])[idx];
                p.x += p1.x + p2.x + p3.x;
                p.y += p1.y + p2.y + p3.y;
                p.z += p1.z + p2.z + p3.z;
                p.w += p1.w + p2.w + p3.w;
                const float m0 = __shfl_sync(0xffffffffu, mval, e * 4 + 0);
                const float m1 = __shfl_sync(0xffffffffu, mval, e * 4 + 1);
                const float m2 = __shfl_sync(0xffffffffu, mval, e * 4 + 2);
                const float m3 = __shfl_sync(0xffffffffu, mval, e * 4 + 3);
                if (f4 & 1u) {
                    v0.x = fmaf(m0, p.x, v0.x); v0.y = fmaf(m0, p.y, v0.y);
                    v0.z = fmaf(m0, p.z, v0.z); v0.w = fmaf(m0, p.w, v0.w); }
                if (f4 & 2u) {
                    v1.x = fmaf(m1, p.x, v1.x); v1.y = fmaf(m1, p.y, v1.y);
                    v1.z = fmaf(m1, p.z, v1.z); v1.w = fmaf(m1, p.w, v1.w); }
                if (f4 & 4u) {
                    v2.x = fmaf(m2, p.x, v2.x); v2.y = fmaf(m2, p.y, v2.y);
                    v2.z = fmaf(m2, p.z, v2.z); v2.w = fmaf(m2, p.w, v2.w); }
                if (f4 & 8u) {
                    v3.x = fmaf(m3, p.x, v3.x); v3.y = fmaf(m3, p.y, v3.y);
                    v3.z = fmaf(m3, p.z, v3.z); v3.w = fmaf(m3, p.w, v3.w); }
            }
        }
    }

    float4* __restrict__ out4 = (float4*)out;
    __stcs(out4 + (long long)(row0 + 0) * (H_ / 4) + tid, v0);
    __stcs(out4 + (long long)(row0 + 1) * (H_ / 4) + tid, v1);
    __stcs(out4 + (long long)(row0 + 2) * (H_ / 4) + tid, v2);
    __stcs(out4 + (long long)(row0 + 3) * (H_ / 4) + tid, v3);
}

// ---------------------------------------------------------------------------
// Launch: single stream; k2 and k3 use Programmatic Stream Serialization so
// their prologues overlap the predecessor (graph-capturable PDL edges).
// ---------------------------------------------------------------------------
extern "C" void kernel_launch(void* const* d_in, const int* in_sizes, int n_in,
                              void* d_out, int out_size) {
    const int*   ids  = (const int*)  d_in[0];
    const float* X    = (const float*)d_in[1];
    const float* msk  = (const float*)d_in[2];
    const float* we   = (const float*)d_in[3];
    const float* W1   = (const float*)d_in[4];
    const float* b1   = (const float*)d_in[5];
    const float* W2   = (const float*)d_in[6];
    const float* b2   = (const float*)d_in[7];
    float* out = (float*)d_out;

    cudaFuncSetAttribute(k1_mma, cudaFuncAttributeMaxDynamicSharedMemorySize, SMEM1);
    cudaFuncSetAttribute(k2_mma, cudaFuncAttributeMaxDynamicSharedMemorySize, SMEM2);

    kprep<<<928, dim3(32, 8)>>>(W2, W1, X);
    k1_mma<<<dim3(8, 8), 128, SMEM1>>>(b1);

    cudaLaunchAttribute pa[1];
    pa[0].id = cudaLaunchAttributeProgrammaticStreamSerialization;
    pa[0].val.programmaticStreamSerializationAllowed = 1;

    cudaLaunchConfig_t c2 = {};
    c2.gridDim = dim3(8, 12, 4);
    c2.blockDim = dim3(128, 1, 1);
    c2.dynamicSmemBytes = SMEM2;
    c2.stream = 0;
    c2.attrs = pa;
    c2.numAttrs = 1;
    cudaLaunchKernelEx(&c2, k2_mma, b2);

    cudaLaunchConfig_t c3 = {};
    c3.gridDim = dim3(4096, 1, 1);
    c3.blockDim = dim3(192, 1, 1);
    c3.dynamicSmemBytes = 0;
    c3.stream = 0;
    c3.attrs = pa;
    c3.numAttrs = 1;
    cudaLaunchKernelEx(&c3, k3_fuse, ids, msk, we, out);
}